// round 10
// baseline (speedup 1.0000x reference)
#include <cuda_runtime.h>

// Fixed problem shapes
#define BB 64
#define CC 64   // C == Co
#define TT 32
#define NN 64
#define KK 3

// smem layout (floats): sX 64x64 (x -> yT), sW 64x68 (WT, padded),
// sAs 64x64 (Asum), sD 3x64 (dinv slabs)
#define SX_OFF  0
#define SW_OFF  4096
#define SWSTR   68
#define SAS_OFF (4096 + 64 * SWSTR)
#define SD_OFF  (SAS_OFF + 4096)
#define SMEM_FLOATS (SD_OFF + 3 * 64)
#define SMEM_BYTES  (SMEM_FLOATS * 4)     // 50,944 B -> 4 CTAs/SM

// One CTA per (b, t). 256 threads, 4x4 register tiles.
// Phase order staggered by bid parity to overlap DRAM (A-phase) with
// compute (GEMM1) across co-resident CTAs.
__global__ void __launch_bounds__(256, 4)
ctg_kernel(const float* __restrict__ x,
           const float* __restrict__ A,
           const float* __restrict__ W,
           const float* __restrict__ bias,
           float* __restrict__ out,
           int copyA)
{
    extern __shared__ float sm[];
    float* sX  = sm + SX_OFF;
    float* sW  = sm + SW_OFF;
    float* sAs = sm + SAS_OFF;
    float* sD  = sm + SD_OFF;

    const int tid = threadIdx.x;
    const int b   = blockIdx.x / TT;
    const int t   = blockIdx.x % TT;
    const int tx  = tid & 15;   // 4-col group
    const int ty  = tid >> 4;   // 4-row group
    const int m0  = tx * 4;

    const size_t abase = (((size_t)b * KK) * TT + t) * (size_t)(NN * NN);
    const size_t kstep = (size_t)TT * NN * NN;
    float* outA = out + (size_t)BB * CC * TT * NN;

    // ---- stage x[b,:,t,:] ([c][n]) and W transposed ([c][o]) ----
    #pragma unroll
    for (int it = 0; it < 4; it++) {
        const int e4 = it * 256 + tid;    // float4 slot 0..1023
        const int r  = e4 >> 4;
        const int c4 = e4 & 15;
        *(float4*)(sX + r * NN + c4 * 4) =
            *(const float4*)(x + (((size_t)(b * CC + r) * TT + t) * NN) + c4 * 4);
        // WT: W[o][c0..c0+3] -> sW[c][o]
        const int o  = r;
        const int c0 = c4 * 4;
        const float4 w = *(const float4*)(W + (size_t)e4 * 4);
        sW[(c0    ) * SWSTR + o] = w.x;
        sW[(c0 + 1) * SWSTR + o] = w.y;
        sW[(c0 + 2) * SWSTR + o] = w.z;
        sW[(c0 + 3) * SWSTR + o] = w.w;
    }
    __syncthreads();

    float acc[4][4];

    // =====================================================================
    // Phase bodies as lambdas (inlined): GEMM1 and A-phase are independent.
    // =====================================================================
    auto gemm1 = [&]() {
        #pragma unroll
        for (int i = 0; i < 4; i++)
            #pragma unroll
            for (int j = 0; j < 4; j++) acc[i][j] = 0.0f;

        #pragma unroll 8
        for (int kk = 0; kk < 64; kk++) {
            const float4 av = *(const float4*)(sX + kk * NN + ty * 4);    // x[kk][4ty..]
            const float4 bv = *(const float4*)(sW + kk * SWSTR + tx * 4); // WT[kk][4tx..]
            const float a0 = av.x, a1 = av.y, a2 = av.z, a3 = av.w;
            acc[0][0] += a0 * bv.x; acc[0][1] += a0 * bv.y; acc[0][2] += a0 * bv.z; acc[0][3] += a0 * bv.w;
            acc[1][0] += a1 * bv.x; acc[1][1] += a1 * bv.y; acc[1][2] += a1 * bv.z; acc[1][3] += a1 * bv.w;
            acc[2][0] += a2 * bv.x; acc[2][1] += a2 * bv.y; acc[2][2] += a2 * bv.z; acc[2][3] += a2 * bv.w;
            acc[3][0] += a3 * bv.x; acc[3][1] += a3 * bv.y; acc[3][2] += a3 * bv.z; acc[3][3] += a3 * bv.w;
        }
        __syncthreads();   // all x reads done before overwriting sX with yT

        const float4 bia = *(const float4*)(bias + tx * 4);
        #pragma unroll
        for (int i = 0; i < 4; i++) {
            float4 r4;
            r4.x = acc[i][0] + bia.x;
            r4.y = acc[i][1] + bia.y;
            r4.z = acc[i][2] + bia.z;
            r4.w = acc[i][3] + bia.w;
            *(float4*)(sX + (4 * ty + i) * NN + tx * 4) = r4;   // yT[n][o]
        }
    };

    auto aphase = [&]() {
        float4 asum[4];
        #pragma unroll
        for (int it = 0; it < 4; it++) { asum[it].x = asum[it].y = asum[it].z = asum[it].w = 0.0f; }

        #pragma unroll
        for (int k = 0; k < KK; k++) {
            const size_t base = abase + k * kstep;
            float* sDk = sD + k * 64;

            float4 a[4];
            #pragma unroll
            for (int it = 0; it < 4; it++) {
                const int e4 = it * 256 + tid;
                a[it] = *(const float4*)(A + base + (size_t)e4 * 4);
                if (copyA) *(float4*)(outA + base + (size_t)e4 * 4) = a[it];
            }

            // row degrees: each half-warp holds one full row (row = it*16 + ty)
            #pragma unroll
            for (int it = 0; it < 4; it++) {
                float s = a[it].x + a[it].y + a[it].z + a[it].w;
                s += __shfl_xor_sync(0xffffffffu, s, 1);
                s += __shfl_xor_sync(0xffffffffu, s, 2);
                s += __shfl_xor_sync(0xffffffffu, s, 4);
                s += __shfl_xor_sync(0xffffffffu, s, 8);
                if (tx == 0) sDk[it * 16 + ty] = rsqrtf(s + 1.0f);   // A_tilde = A + I
            }
            __syncthreads();

            const float4 dm = *(const float4*)(sDk + m0);
            #pragma unroll
            for (int it = 0; it < 4; it++) {
                const int n = it * 16 + ty;
                const float dn = sDk[n];
                float4 v = a[it];
                const int d = n - m0;
                if (d == 0) v.x += 1.0f;
                if (d == 1) v.y += 1.0f;
                if (d == 2) v.z += 1.0f;
                if (d == 3) v.w += 1.0f;
                asum[it].x += v.x * dn * dm.x;
                asum[it].y += v.y * dn * dm.y;
                asum[it].z += v.z * dn * dm.z;
                asum[it].w += v.w * dn * dm.w;
            }
            // no trailing sync: next k uses a different sD slab
        }

        #pragma unroll
        for (int it = 0; it < 4; it++)
            *(float4*)(sAs + (it * 16 + ty) * NN + m0) = asum[it];
    };

    // ---- staggered phase order: halves the DRAM burst synchronization ----
    if (blockIdx.x & 1) {
        aphase();
        __syncthreads();
        gemm1();
    } else {
        gemm1();
        __syncthreads();
        aphase();
    }
    __syncthreads();   // yT (sX) and Asum (sAs) both visible

    // ---- GEMM2: x_out[c][m] = sum_n yT[n][c] * Asum[n][m] ----
    #pragma unroll
    for (int i = 0; i < 4; i++)
        #pragma unroll
        for (int j = 0; j < 4; j++) acc[i][j] = 0.0f;

    #pragma unroll 8
    for (int kk = 0; kk < 64; kk++) {
        const float4 av = *(const float4*)(sX  + kk * NN + ty * 4); // yT[kk][4ty..]
        const float4 bv = *(const float4*)(sAs + kk * NN + tx * 4); // Asum[kk][4tx..]
        const float a0 = av.x, a1 = av.y, a2 = av.z, a3 = av.w;
        acc[0][0] += a0 * bv.x; acc[0][1] += a0 * bv.y; acc[0][2] += a0 * bv.z; acc[0][3] += a0 * bv.w;
        acc[1][0] += a1 * bv.x; acc[1][1] += a1 * bv.y; acc[1][2] += a1 * bv.z; acc[1][3] += a1 * bv.w;
        acc[2][0] += a2 * bv.x; acc[2][1] += a2 * bv.y; acc[2][2] += a2 * bv.z; acc[2][3] += a2 * bv.w;
        acc[3][0] += a3 * bv.x; acc[3][1] += a3 * bv.y; acc[3][2] += a3 * bv.z; acc[3][3] += a3 * bv.w;
    }

    #pragma unroll
    for (int i = 0; i < 4; i++) {
        const int c = 4 * ty + i;
        float4 r4;
        r4.x = acc[i][0]; r4.y = acc[i][1]; r4.z = acc[i][2]; r4.w = acc[i][3];
        *(float4*)(out + (((size_t)(b * CC + c) * TT + t) * NN) + m0) = r4;
    }
}

extern "C" void kernel_launch(void* const* d_in, const int* in_sizes, int n_in,
                              void* d_out, int out_size)
{
    const float* x    = (const float*)d_in[0];
    const float* A    = (const float*)d_in[1];
    const float* W    = (const float*)d_in[2];
    const float* bias = (const float*)d_in[3];
    float* out = (float*)d_out;

    const int xout_elems = BB * CC * TT * NN;           // 8,388,608
    const int copyA = (out_size > xout_elems) ? 1 : 0;  // tuple output (x_out, A)

    cudaFuncSetAttribute(ctg_kernel, cudaFuncAttributeMaxDynamicSharedMemorySize, SMEM_BYTES);
    ctg_kernel<<<BB * TT, 256, SMEM_BYTES>>>(x, A, W, bias, out, copyA);
}